// round 14
// baseline (speedup 1.0000x reference)
#include <cuda_runtime.h>
#include <cuda_bf16.h>
#include <cstdint>
#include <math.h>

// Problem constants
#define B_  256
#define E_  256
#define H_  512
#define V_  32768
#define T_  8
#define LN_EPS 1e-5f
#define RMS_EPS 1.1920928955078125e-7f   // finfo(f32).eps
#define TINY_F 1.17549435e-38f

#define ZSPLIT 32                         // split-K factor for expected GEMM
#define KC_TOT 2048                       // V/16 k-chunks
#define EA_SZ (16 * KC_TOT * 32)          // per-slot A-frag words (rb16=16)

// ---------------- device scratch (static, allocation-free) ----------------
__device__ __align__(16) float g_h[B_ * H_];                 // residual h (fp32 exact)
__device__ float g_zinv[B_];
__device__ float g_cinv[V_];
__device__ __align__(16) uint4 g_afrag[32 * 1024];           // logits A frags
__device__ __align__(16) uint4 g_bfrag[(size_t)512 * 8 * 32 * 32];  // logits B frags (64MB)
__device__ __align__(16) uint32_t g_ea0[EA_SZ];              // expected A frags (e), slot (r,c)
__device__ __align__(16) uint32_t g_ea1[EA_SZ];              // slot (r+8,c)
__device__ __align__(16) uint32_t g_ea2[EA_SZ];              // slot (r,c+8)
__device__ __align__(16) uint32_t g_ea3[EA_SZ];              // slot (r+8,c+8)
__device__ __align__(16) uint4 g_ctfrag[(size_t)32 * KC_TOT * 32];  // CT B frags (32MB)
__device__ __align__(16) float g_partial[ZSPLIT * B_ * H_];       // split-K partials (raw-e sums)
__device__ __align__(16) float g_expv[(size_t)B_ * V_];           // exp((l+g)/tau) fp32
__device__ __align__(16) float g_psum[B_ * 512 * 2];              // per (b, vtile, wn) sums
__device__ float g_rsum[B_];                                       // 1/rowsum

// ================= PTX helpers (base ISA only) =================
__device__ __forceinline__ void mma_bf16(float* d, const uint32_t* a, const uint32_t* b) {
    asm volatile(
        "mma.sync.aligned.m16n8k16.row.col.f32.bf16.bf16.f32 "
        "{%0,%1,%2,%3}, {%4,%5,%6,%7}, {%8,%9}, {%0,%1,%2,%3};"
        : "+f"(d[0]), "+f"(d[1]), "+f"(d[2]), "+f"(d[3])
        : "r"(a[0]), "r"(a[1]), "r"(a[2]), "r"(a[3]), "r"(b[0]), "r"(b[1]));
}
__device__ __forceinline__ uint32_t pk2(__nv_bfloat16 a, __nv_bfloat16 b) {
    __nv_bfloat162 t;
    t.x = a; t.y = b;
    return *(uint32_t*)&t;
}
__device__ __forceinline__ __nv_bfloat16 qsplit(float f, int type) {
    __nv_bfloat16 h = __float2bfloat16(f);
    if (type) return __float2bfloat16(f - __bfloat162float(h));
    return h;
}

// ---------------- reductions ----------------
__device__ __forceinline__ float blockReduceSum(float v, float* sh) {
    __syncthreads();
    int lane = threadIdx.x & 31, wid = threadIdx.x >> 5;
#pragma unroll
    for (int o = 16; o; o >>= 1) v += __shfl_xor_sync(0xFFFFFFFFu, v, o);
    if (lane == 0) sh[wid] = v;
    __syncthreads();
    int nw = blockDim.x >> 5;
    if (wid == 0) {
        float s = (lane < nw) ? sh[lane] : 0.f;
#pragma unroll
        for (int o = 16; o; o >>= 1) s += __shfl_xor_sync(0xFFFFFFFFu, s, o);
        if (lane == 0) sh[0] = s;
    }
    __syncthreads();
    float r = sh[0];
    __syncthreads();
    return r;
}

// ---------------- Threefry-2x32 (JAX partitionable, key=(0,42)) ----------------
__device__ __forceinline__ unsigned rotl32(unsigned x, int r) { return __funnelshift_l(x, x, r); }
__device__ __forceinline__ uint2 tf2x32(unsigned x0, unsigned x1) {
    const unsigned k0 = 0u, k1 = 42u;
    const unsigned k2 = k0 ^ k1 ^ 0x1BD11BDAu;
    x0 += k0; x1 += k1;
#define TFR(r) { x0 += x1; x1 = rotl32(x1, r); x1 ^= x0; }
    TFR(13) TFR(15) TFR(26) TFR(6)
    x0 += k1; x1 += k2 + 1u;
    TFR(17) TFR(29) TFR(16) TFR(24)
    x0 += k2; x1 += k0 + 2u;
    TFR(13) TFR(15) TFR(26) TFR(6)
    x0 += k0; x1 += k1 + 3u;
    TFR(17) TFR(29) TFR(16) TFR(24)
    x0 += k1; x1 += k2 + 4u;
    TFR(13) TFR(15) TFR(26) TFR(6)
    x0 += k2; x1 += k0 + 5u;
#undef TFR
    return make_uint2(x0, x1);
}
// gumbel = -log(-log(u)); exact-argument log1p poly near u->1, __logf elsewhere.
__device__ __forceinline__ float gumbel_val(unsigned t, unsigned b, unsigned v) {
    unsigned f = (((t << 8) | b) << 15) | v;
    uint2 r = tf2x32(0u, f);
    unsigned bits = r.x ^ r.y;
    unsigned m = bits >> 9;
    float x = __uint_as_float(0x3F800000u | m);
    float u = x - 1.0f;                 // uniform in [0,1), exact
    float d = x - 2.0f;                 // u - 1, exact
    float p = fmaf(-0.25f, d, 0.33333333f);
    p = fmaf(p, d, -0.5f);
    p = fmaf(p, d, 1.0f);
    p = -p * d;
    float l = -__logf(u);
    float y = (d > -0.0625f) ? p : l;
    y = (m == 0u) ? 87.3365448f : y;
    return -__logf(y);
}
__device__ __forceinline__ float tau_value(const void* p) {
    int i = *(const int*)p;
    float f = __int_as_float(i);
    if (f > 1e-3f && f < 1e6f) return f;
    return (float)i;
}

// ---------------- backbone: h = GELU(LN(x@W1 + b1)) ----------------
__global__ void __launch_bounds__(512) backbone_kernel(
    const float* __restrict__ x, const float* __restrict__ W1,
    const float* __restrict__ b1, const float* __restrict__ ln_g,
    const float* __restrict__ ln_b) {
    __shared__ float xs[E_];
    __shared__ float sred[32];
    int b = blockIdx.x, col = threadIdx.x;
    if (col < E_) xs[col] = x[b * E_ + col];
    __syncthreads();
    float acc = b1[col];
#pragma unroll 4
    for (int e = 0; e < E_; e++) acc = fmaf(xs[e], W1[e * H_ + col], acc);
    float mu = blockReduceSum(acc, sred) * (1.0f / H_);
    float d = acc - mu;
    float var = blockReduceSum(d * d, sred) * (1.0f / H_);
    float nrm = d / sqrtf(var + LN_EPS) * ln_g[col] + ln_b[col];
    float hv = 0.5f * nrm * (1.0f + erff(nrm * 0.70710678118654752f));
    g_h[b * H_ + col] = hv;
    float n2 = blockReduceSum(hv * hv, sred);
    if (col == 0) g_zinv[b] = 1.0f / fmaxf(sqrtf(n2), 1e-12f);
}

// ---------------- A-fragment packing for logits (wide grid: 128 x 256) ----------------
__global__ void __launch_bounds__(256) afrag_kernel() {
    int combo = blockIdx.x >> 2;
    int type = combo & 1;
    int mi = (combo >> 1) & 1, wm = (combo >> 2) & 3, xtile = combo >> 4;
    int ks = ((blockIdx.x & 3) << 3) | (threadIdx.x >> 5);
    int lane = threadIdx.x & 31;
    int r = xtile * 128 + wm * 32 + mi * 16 + (lane >> 2);
    int c = ks * 16 + (lane & 3) * 2;
    const float* Hp = g_h;
    uint4 o;
    o.x = pk2(qsplit(Hp[r * H_ + c], type),           qsplit(Hp[r * H_ + c + 1], type));
    o.y = pk2(qsplit(Hp[(r + 8) * H_ + c], type),     qsplit(Hp[(r + 8) * H_ + c + 1], type));
    o.z = pk2(qsplit(Hp[r * H_ + c + 8], type),       qsplit(Hp[r * H_ + c + 9], type));
    o.w = pk2(qsplit(Hp[(r + 8) * H_ + c + 8], type), qsplit(Hp[(r + 8) * H_ + c + 9], type));
    g_afrag[(size_t)combo * 1024 + ks * 32 + lane] = o;
}

// ---------------- codebook row inverse norms ----------------
__global__ void __launch_bounds__(256) cinv_kernel(const float* __restrict__ C) {
    int warp = blockIdx.x * 8 + (threadIdx.x >> 5);
    int lane = threadIdx.x & 31;
    if (warp >= V_) return;
    const float* row = C + (size_t)warp * H_;
    float ss = 0.f;
#pragma unroll 4
    for (int i = lane; i < H_; i += 32) { float v = row[i]; ss = fmaf(v, v, ss); }
#pragma unroll
    for (int o = 16; o; o >>= 1) ss += __shfl_xor_sync(0xFFFFFFFFu, ss, o);
    if (lane == 0) g_cinv[warp] = 1.0f / fmaxf(sqrtf(ss), 1e-12f);
}

// ---------------- codebook prep: logits B frags + expected CT B frags ----------------
__global__ void __launch_bounds__(256) prep_kernel(const float* __restrict__ C) {
    __shared__ float tile[32][33];   // tile[v-local][h-local]
    int v0 = blockIdx.x * 32, h0 = blockIdx.y * 32;
    int tx = threadIdx.x & 31, ty = threadIdx.x >> 5;
#pragma unroll
    for (int j = 0; j < 4; j++) {
        int v = v0 + ty + j * 8;
        tile[ty + j * 8][tx] = C[(size_t)v * H_ + h0 + tx];
    }
    __syncthreads();
    // ---- logits B fragment emission (n = v, k = h): 256 threads ----
    {
        int fb = threadIdx.x >> 6;           // kshalf = fb>>1, nj = fb&1
        int kshalf = fb >> 1, nj = fb & 1;
        int type = (threadIdx.x >> 5) & 1;
        int lane = threadIdx.x & 31;
        int nl = nj * 16 + (lane >> 2);
        int kl = kshalf * 16 + (lane & 3) * 2;
        uint4 o;
        o.x = pk2(qsplit(tile[nl][kl], type),         qsplit(tile[nl][kl + 1], type));
        o.y = pk2(qsplit(tile[nl][kl + 8], type),     qsplit(tile[nl][kl + 9], type));
        o.z = pk2(qsplit(tile[nl + 8][kl], type),     qsplit(tile[nl + 8][kl + 1], type));
        o.w = pk2(qsplit(tile[nl + 8][kl + 8], type), qsplit(tile[nl + 8][kl + 9], type));
        int vtile = v0 >> 6, wn = (v0 >> 5) & 1;
        int ks = (h0 >> 4) + kshalf;
        size_t idx = ((((size_t)vtile * 8) + wn * 4 + nj * 2 + type) * 32 + ks) * 32 + lane;
        g_bfrag[idx] = o;
    }
    // ---- expected CT B fragment emission (n = h, k = v): 128 threads ----
    if (threadIdx.x < 128) {
        int fb = threadIdx.x >> 5;           // nj' = fb&1, kj' = fb>>1
        int nj = fb & 1, kj = fb >> 1;
        int lane = threadIdx.x & 31;
        int nl = nj * 16 + (lane >> 2);      // local h
        int kl = kj * 16 + (lane & 3) * 2;   // local v
        uint4 o;
        o.x = pk2(__float2bfloat16(tile[kl][nl]),     __float2bfloat16(tile[kl + 1][nl]));
        o.y = pk2(__float2bfloat16(tile[kl + 8][nl]), __float2bfloat16(tile[kl + 9][nl]));
        o.z = pk2(__float2bfloat16(tile[kl][nl + 8]),     __float2bfloat16(tile[kl + 1][nl + 8]));
        o.w = pk2(__float2bfloat16(tile[kl + 8][nl + 8]), __float2bfloat16(tile[kl + 9][nl + 8]));
        int h16 = (h0 >> 4) + nj;
        int kc = (v0 >> 4) + kj;
        g_ctfrag[(((size_t)h16 * KC_TOT) + kc) * 32 + lane] = o;
    }
}

// ================= logits GEMM: fragment-packed LDG, NO shared memory =================
__global__ void __launch_bounds__(256, 2) logits_mma_kernel(
    const float* __restrict__ lscale, float* __restrict__ out,
    const void* __restrict__ taup, int t) {
    const int tid = threadIdx.x, lane = tid & 31, wid = tid >> 5;
    const int wm = wid >> 1, wn = wid & 1;
    const int xtile = blockIdx.x, vtile = blockIdx.y;
    const int bbase = xtile * 128, vbase = vtile * 64;

    float acc[2][4][4];
#pragma unroll
    for (int i = 0; i < 2; i++)
#pragma unroll
        for (int j = 0; j < 4; j++)
#pragma unroll
            for (int c = 0; c < 4; c++) acc[i][j][c] = 0.f;

    const char* pA = (const char*)g_afrag +
                     ((size_t)(xtile * 16 + wm * 4) * 1024 + lane) * 16;
    const char* pB = (const char*)g_bfrag +
                     (((size_t)vtile * 8 + wn * 4) * 1024 + lane) * 16;

#define LDA(buf, ks) do { \
        buf[0][0] = *(const uint4*)(pA + (ks) * 512); \
        buf[0][1] = *(const uint4*)(pA + 16384 + (ks) * 512); \
        buf[1][0] = *(const uint4*)(pA + 32768 + (ks) * 512); \
        buf[1][1] = *(const uint4*)(pA + 49152 + (ks) * 512); \
    } while (0)
#define LDB(buf, ks) do { \
        buf[0][0] = *(const uint4*)(pB + (ks) * 512); \
        buf[0][1] = *(const uint4*)(pB + 16384 + (ks) * 512); \
        buf[1][0] = *(const uint4*)(pB + 32768 + (ks) * 512); \
        buf[1][1] = *(const uint4*)(pB + 49152 + (ks) * 512); \
    } while (0)
#define COMPUTE(A_, B_) do { \
        _Pragma("unroll") \
        for (int mi_ = 0; mi_ < 2; mi_++) { \
            const uint32_t* ah_ = (const uint32_t*)&A_[mi_][0]; \
            const uint32_t* al_ = (const uint32_t*)&A_[mi_][1]; \
            _Pragma("unroll") \
            for (int nf_ = 0; nf_ < 4; nf_++) { \
                const uint32_t* bh_ = ((const uint32_t*)&B_[nf_ >> 1][0]) + (nf_ & 1) * 2; \
                const uint32_t* bl_ = ((const uint32_t*)&B_[nf_ >> 1][1]) + (nf_ & 1) * 2; \
                mma_bf16(acc[mi_][nf_], ah_, bh_); \
                mma_bf16(acc[mi_][nf_], ah_, bl_); \
                mma_bf16(acc[mi_][nf_], al_, bh_); \
            } \
        } \
    } while (0)

    uint4 A0[2][2], B0[2][2], A1[2][2], B1[2][2];
    LDA(A0, 0); LDB(B0, 0);
#pragma unroll
    for (int ks = 0; ks < 32; ks += 2) {
        if (ks + 1 < 32) { LDA(A1, ks + 1); LDB(B1, ks + 1); }
        COMPUTE(A0, B0);
        if (ks + 2 < 32) { LDA(A0, ks + 2); LDB(B0, ks + 2); }
        if (ks + 1 < 32) COMPUTE(A1, B1);
    }
#undef LDA
#undef LDB
#undef COMPUTE

    // ---- epilogue: logits + gumbel + exp; e -> fp32 rows + A-frag layout for expected ----
    float scale = expf(__ldg(lscale + t));
    float inv_tau = 1.0f / tau_value(taup);
#pragma unroll
    for (int mi = 0; mi < 2; mi++) {
        int r0 = bbase + wm * 32 + mi * 16 + (lane >> 2);
        int r1 = r0 + 8;
        int rb16 = (bbase + wm * 32 + mi * 16) >> 4;
        float z0 = g_zinv[r0], z1 = g_zinv[r1];
        float* row0 = out + (((size_t)r0 * T_ + t) << 15);
        float* row1 = out + (((size_t)r1 * T_ + t) << 15);
        float* e0 = g_expv + (size_t)r0 * V_;
        float* e1 = g_expv + (size_t)r1 * V_;
        float s0 = 0.f, s1 = 0.f;
#pragma unroll
        for (int nf = 0; nf < 4; nf++) {
            int v0 = vbase + wn * 32 + nf * 8 + (lane & 3) * 2;
            float cv0 = g_cinv[v0] * scale, cv1 = g_cinv[v0 + 1] * scale;
            float l00 = acc[mi][nf][0] * z0 * cv0, l01 = acc[mi][nf][1] * z0 * cv1;
            float l10 = acc[mi][nf][2] * z1 * cv0, l11 = acc[mi][nf][3] * z1 * cv1;
            *(float2*)(row0 + v0) = make_float2(l00, l01);
            *(float2*)(row1 + v0) = make_float2(l10, l11);
            float e00 = __expf((l00 + gumbel_val(t, r0, v0))     * inv_tau);
            float e01 = __expf((l01 + gumbel_val(t, r0, v0 + 1)) * inv_tau);
            float e10 = __expf((l10 + gumbel_val(t, r1, v0))     * inv_tau);
            float e11 = __expf((l11 + gumbel_val(t, r1, v0 + 1)) * inv_tau);
            *(float2*)(e0 + v0) = make_float2(e00, e01);
            *(float2*)(e1 + v0) = make_float2(e10, e11);
            // e -> expected-GEMM A fragments (coalesced across lanes)
            int kc = (vbase + wn * 32 + nf * 8) >> 4;
            size_t fidx = ((size_t)rb16 * KC_TOT + kc) * 32 + lane;
            if (nf & 1) {
                g_ea2[fidx] = pk2(__float2bfloat16(e00), __float2bfloat16(e01));
                g_ea3[fidx] = pk2(__float2bfloat16(e10), __float2bfloat16(e11));
            } else {
                g_ea0[fidx] = pk2(__float2bfloat16(e00), __float2bfloat16(e01));
                g_ea1[fidx] = pk2(__float2bfloat16(e10), __float2bfloat16(e11));
            }
            s0 += e00 + e01;
            s1 += e10 + e11;
        }
        s0 += __shfl_xor_sync(0xFFFFFFFFu, s0, 1);
        s0 += __shfl_xor_sync(0xFFFFFFFFu, s0, 2);
        s1 += __shfl_xor_sync(0xFFFFFFFFu, s1, 1);
        s1 += __shfl_xor_sync(0xFFFFFFFFu, s1, 2);
        if ((lane & 3) == 0) {
            g_psum[((size_t)r0 * 512 + vtile) * 2 + wn] = s0;
            g_psum[((size_t)r1 * 512 + vtile) * 2 + wn] = s1;
        }
    }
}

// ---------------- row sums (deterministic, tiny) ----------------
__global__ void __launch_bounds__(256) rowsum_kernel() {
    int b = blockIdx.x * 8 + (threadIdx.x >> 5);
    int lane = threadIdx.x & 31;
    const float* p = g_psum + (size_t)b * 1024;
    float s = 0.f;
#pragma unroll
    for (int i = 0; i < 32; i++) s += p[lane + i * 32];
#pragma unroll
    for (int o = 16; o; o >>= 1) s += __shfl_xor_sync(0xFFFFFFFFu, s, o);
    if (lane == 0) g_rsum[b] = 1.0f / s;
}

// ---------------- normalize: p = e * rsum (fp32 probs output only, wide grid) ----------------
__global__ void __launch_bounds__(256) normalize_kernel(float* __restrict__ outw, int t) {
    int i = (blockIdx.x * 256 + threadIdx.x) * 4;
    int b = i >> 15, v = i & (V_ - 1);
    float4 e = *(const float4*)(g_expv + (size_t)b * V_ + v);
    float rs = g_rsum[b];
    *(float4*)(outw + (size_t)B_ * T_ * V_ + (((size_t)b * T_ + t) << 15) + v) =
        make_float4(e.x * rs, e.y * rs, e.z * rs, e.w * rs);
}

// ================= expected GEMM: fragment-packed LDG, NO shared memory =================
// CTA tile 128b x 64h, z-slice K=1024 (64 k-chunks). Warps 4m x 2n.
__global__ void __launch_bounds__(256, 2) expected_mma_kernel() {
    const int tid = threadIdx.x, lane = tid & 31, wid = tid >> 5;
    const int wm = wid >> 1, wn = wid & 1;
    const int hbase = blockIdx.x * 64, bbase = blockIdx.y * 128;
    const int z = blockIdx.z;
    const int kc0 = z * 64;

    float acc[2][4][4];
#pragma unroll
    for (int i = 0; i < 2; i++)
#pragma unroll
        for (int j = 0; j < 4; j++)
#pragma unroll
            for (int c = 0; c < 4; c++) acc[i][j][c] = 0.f;

    const size_t bA0 = ((size_t)((bbase >> 4) + wm * 2) * KC_TOT + kc0) * 32 + lane;
    const size_t bA1 = bA0 + (size_t)KC_TOT * 32;
    const uint4* pB0 = g_ctfrag + (((size_t)((hbase >> 4) + wn * 2) * KC_TOT) + kc0) * 32 + lane;
    const uint4* pB1 = pB0 + (size_t)KC_TOT * 32;

#define LDE(A_, B_, kc) do { \
        int off_ = (kc) * 32; \
        A_[0][0] = g_ea0[bA0 + off_]; A_[0][1] = g_ea1[bA0 + off_]; \
        A_[0][2] = g_ea2[bA0 + off_]; A_[0][3] = g_ea3[bA0 + off_]; \
        A_[1][0] = g_ea0[bA1 + off_]; A_[1][1] = g_ea1[bA1 + off_]; \
        A_[1][2] = g_ea2[bA1 + off_]; A_[1][3] = g_ea3[bA1 + off_]; \
        B_[0] = pB0[off_]; B_[1] = pB1[off_]; \
    } while (0)
#define CMPE(A_, B_) do { \
        _Pragma("unroll") \
        for (int mi_ = 0; mi_ < 2; mi_++) \
            _Pragma("unroll") \
            for (int nf_ = 0; nf_ < 4; nf_++) \
                mma_bf16(acc[mi_][nf_], A_[mi_], \
                         ((const uint32_t*)&B_[nf_ >> 1]) + (nf_ & 1) * 2); \
    } while (0)

    uint32_t A0[2][4], A1[2][4];
    uint4 B0[2], B1[2];
    LDE(A0, B0, 0);
#pragma unroll 4
    for (int kc = 0; kc < 64; kc += 2) {
        if (kc + 1 < 64) LDE(A1, B1, kc + 1);
        CMPE(A0, B0);
        if (kc + 2 < 64) LDE(A0, B0, kc + 2);
        if (kc + 1 < 64) CMPE(A1, B1);
    }
#undef LDE
#undef CMPE

#pragma unroll
    for (int mi = 0; mi < 2; mi++) {
        int r0 = bbase + wm * 32 + mi * 16 + (lane >> 2);
        float* p0 = g_partial + ((size_t)z * B_ + r0) * H_ + hbase;
        float* p1 = g_partial + ((size_t)z * B_ + r0 + 8) * H_ + hbase;
#pragma unroll
        for (int nf = 0; nf < 4; nf++) {
            int h0 = wn * 32 + nf * 8 + (lane & 3) * 2;
            *(float2*)(p0 + h0) = make_float2(acc[mi][nf][0], acc[mi][nf][1]);
            *(float2*)(p1 + h0) = make_float2(acc[mi][nf][2], acc[mi][nf][3]);
        }
    }
}

// ---------------- residual update + RMSNorm (folds exp(gamma)*rsum into raw-e sums) ----------------
__global__ void __launch_bounds__(512) update_kernel(
    const float* __restrict__ gamma, const float* __restrict__ rms_w, int t) {
    __shared__ float sred[32];
    int b = blockIdx.x, h = threadIdx.x;
    float e = 0.f;
#pragma unroll
    for (int s = 0; s < ZSPLIT; s++) e += g_partial[((size_t)s * B_ + b) * H_ + h];
    float eg = expf(gamma[t]) * g_rsum[b];
    float hn = g_h[b * H_ + h] - eg * e;
    float ss = blockReduceSum(hn * hn, sred);
    float denom = sqrtf(ss * (1.0f / H_) + RMS_EPS);
    float hv = hn / denom * rms_w[h];
    g_h[b * H_ + h] = hv;
    float n2 = blockReduceSum(hv * hv, sred);
    if (h == 0) g_zinv[b] = 1.0f / fmaxf(sqrtf(n2), 1e-12f);
}

// ---------------- launch ----------------
extern "C" void kernel_launch(void* const* d_in, const int* in_sizes, int n_in,
                              void* d_out, int out_size) {
    const float* x           = (const float*)d_in[0];
    const float* W1          = (const float*)d_in[1];
    const float* b1          = (const float*)d_in[2];
    const float* ln_g        = (const float*)d_in[3];
    const float* ln_b        = (const float*)d_in[4];
    const float* codebook    = (const float*)d_in[5];
    const float* logit_scale = (const float*)d_in[6];
    const float* gamma       = (const float*)d_in[7];
    const float* rms_w       = (const float*)d_in[8];
    const void*  tau         = d_in[9];
    float* out = (float*)d_out;

    const long long logitsElems = (long long)B_ * T_ * V_;
    int writeProbs = ((long long)out_size >= 2 * logitsElems) ? 1 : 0;

    backbone_kernel<<<B_, 512>>>(x, W1, b1, ln_g, ln_b);
    cinv_kernel<<<V_ / 8, 256>>>(codebook);
    prep_kernel<<<dim3(V_ / 32, H_ / 32), 256>>>(codebook);
    afrag_kernel<<<128, 256>>>();

    for (int t = 0; t < T_; t++) {
        logits_mma_kernel<<<dim3(B_ / 128, V_ / 64), 256>>>(logit_scale, out, tau, t);
        rowsum_kernel<<<B_ / 8, 256>>>();
        if (writeProbs) normalize_kernel<<<(B_ * V_ / 4) / 256, 256>>>(out, t);
        if (t < T_ - 1) {
            expected_mma_kernel<<<dim3(H_ / 64, B_ / 128, ZSPLIT), 256>>>();
            update_kernel<<<B_, 512>>>(gamma, rms_w, t);
            afrag_kernel<<<128, 256>>>();
        }
    }
}

// round 15
// speedup vs baseline: 1.3120x; 1.3120x over previous
#include <cuda_runtime.h>
#include <cuda_bf16.h>
#include <cuda_fp16.h>
#include <cstdint>
#include <math.h>

// Problem constants
#define B_  256
#define E_  256
#define H_  512
#define V_  32768
#define T_  8
#define LN_EPS 1e-5f
#define RMS_EPS 1.1920928955078125e-7f   // finfo(f32).eps
#define TINY_F 1.17549435e-38f

#define ZSPLIT 32                         // split-K factor for expected GEMM

// ---------------- device scratch (static, allocation-free) ----------------
__device__ __align__(16) float g_h[B_ * H_];                 // residual h (fp32 exact)
__device__ float g_zinv[B_];
__device__ float g_cinv[V_];
__device__ __align__(16) uint4 g_afrag[16 * 1024];           // logits A frags (fp16)
__device__ __align__(16) uint4 g_bfrag[(size_t)512 * 4 * 32 * 32];  // logits B frags fp16 (32MB)
__device__ __align__(16) __nv_bfloat16 g_CT[(size_t)H_ * V_];     // codebook^T bf16 [H][V]
__device__ __align__(16) __nv_bfloat16 g_e_bf16[(size_t)B_ * V_]; // bf16(raw e) for expected GEMM
__device__ __align__(16) float g_partial[ZSPLIT * B_ * H_];       // split-K partials (raw-e sums)
__device__ __align__(16) float g_expv[(size_t)B_ * V_];           // exp((l+g)/tau) fp32
__device__ __align__(16) float g_psum[B_ * 512 * 2];              // per (b, vtile, wn) sums
__device__ float g_rsum[B_];                                       // 1/rowsum

// ================= PTX helpers (base ISA only) =================
__device__ __forceinline__ uint32_t smem_u32(const void* p) {
    uint32_t a;
    asm("{ .reg .u64 t; cvta.to.shared.u64 t, %1; cvt.u32.u64 %0, t; }" : "=r"(a) : "l"(p));
    return a;
}
__device__ __forceinline__ void cp16(uint32_t dst, const void* src) {
    asm volatile("cp.async.cg.shared.global [%0], [%1], 16;" :: "r"(dst), "l"(src) : "memory");
}
#define CP_COMMIT() asm volatile("cp.async.commit_group;" ::: "memory")
#define CP_WAIT1()  asm volatile("cp.async.wait_group 1;" ::: "memory")

__device__ __forceinline__ void ldsm4(uint32_t* r, uint32_t addr) {
    asm volatile("ldmatrix.sync.aligned.m8n8.x4.shared.b16 {%0,%1,%2,%3}, [%4];"
                 : "=r"(r[0]), "=r"(r[1]), "=r"(r[2]), "=r"(r[3]) : "r"(addr));
}
__device__ __forceinline__ void mma_bf16(float* d, const uint32_t* a, const uint32_t* b) {
    asm volatile(
        "mma.sync.aligned.m16n8k16.row.col.f32.bf16.bf16.f32 "
        "{%0,%1,%2,%3}, {%4,%5,%6,%7}, {%8,%9}, {%0,%1,%2,%3};"
        : "+f"(d[0]), "+f"(d[1]), "+f"(d[2]), "+f"(d[3])
        : "r"(a[0]), "r"(a[1]), "r"(a[2]), "r"(a[3]), "r"(b[0]), "r"(b[1]));
}
__device__ __forceinline__ void mma_f16(float* d, const uint32_t* a, const uint32_t* b) {
    asm volatile(
        "mma.sync.aligned.m16n8k16.row.col.f32.f16.f16.f32 "
        "{%0,%1,%2,%3}, {%4,%5,%6,%7}, {%8,%9}, {%0,%1,%2,%3};"
        : "+f"(d[0]), "+f"(d[1]), "+f"(d[2]), "+f"(d[3])
        : "r"(a[0]), "r"(a[1]), "r"(a[2]), "r"(a[3]), "r"(b[0]), "r"(b[1]));
}
__device__ __forceinline__ uint32_t pk2(__nv_bfloat16 a, __nv_bfloat16 b) {
    __nv_bfloat162 t;
    t.x = a; t.y = b;
    return *(uint32_t*)&t;
}
__device__ __forceinline__ uint32_t pk2h(float a, float b) {
    __half2 t;
    t.x = __float2half(a); t.y = __float2half(b);
    return *(uint32_t*)&t;
}

// ---------------- reductions ----------------
__device__ __forceinline__ float blockReduceSum(float v, float* sh) {
    __syncthreads();
    int lane = threadIdx.x & 31, wid = threadIdx.x >> 5;
#pragma unroll
    for (int o = 16; o; o >>= 1) v += __shfl_xor_sync(0xFFFFFFFFu, v, o);
    if (lane == 0) sh[wid] = v;
    __syncthreads();
    int nw = blockDim.x >> 5;
    if (wid == 0) {
        float s = (lane < nw) ? sh[lane] : 0.f;
#pragma unroll
        for (int o = 16; o; o >>= 1) s += __shfl_xor_sync(0xFFFFFFFFu, s, o);
        if (lane == 0) sh[0] = s;
    }
    __syncthreads();
    float r = sh[0];
    __syncthreads();
    return r;
}

// ---------------- Threefry-2x32 (JAX partitionable, key=(0,42)) ----------------
__device__ __forceinline__ unsigned rotl32(unsigned x, int r) { return __funnelshift_l(x, x, r); }
__device__ __forceinline__ uint2 tf2x32(unsigned x0, unsigned x1) {
    const unsigned k0 = 0u, k1 = 42u;
    const unsigned k2 = k0 ^ k1 ^ 0x1BD11BDAu;
    x0 += k0; x1 += k1;
#define TFR(r) { x0 += x1; x1 = rotl32(x1, r); x1 ^= x0; }
    TFR(13) TFR(15) TFR(26) TFR(6)
    x0 += k1; x1 += k2 + 1u;
    TFR(17) TFR(29) TFR(16) TFR(24)
    x0 += k2; x1 += k0 + 2u;
    TFR(13) TFR(15) TFR(26) TFR(6)
    x0 += k0; x1 += k1 + 3u;
    TFR(17) TFR(29) TFR(16) TFR(24)
    x0 += k1; x1 += k2 + 4u;
    TFR(13) TFR(15) TFR(26) TFR(6)
    x0 += k2; x1 += k0 + 5u;
#undef TFR
    return make_uint2(x0, x1);
}
// gumbel = -log(-log(u)); exact-argument log1p poly near u->1, __logf elsewhere.
__device__ __forceinline__ float gumbel_val(unsigned t, unsigned b, unsigned v) {
    unsigned f = (((t << 8) | b) << 15) | v;
    uint2 r = tf2x32(0u, f);
    unsigned bits = r.x ^ r.y;
    unsigned m = bits >> 9;
    float x = __uint_as_float(0x3F800000u | m);
    float u = x - 1.0f;                 // uniform in [0,1), exact
    float d = x - 2.0f;                 // u - 1, exact
    float p = fmaf(-0.25f, d, 0.33333333f);
    p = fmaf(p, d, -0.5f);
    p = fmaf(p, d, 1.0f);
    p = -p * d;
    float l = -__logf(u);
    float y = (d > -0.0625f) ? p : l;
    y = (m == 0u) ? 87.3365448f : y;
    return -__logf(y);
}
__device__ __forceinline__ float tau_value(const void* p) {
    int i = *(const int*)p;
    float f = __int_as_float(i);
    if (f > 1e-3f && f < 1e6f) return f;
    return (float)i;
}

// ---------------- backbone: h = GELU(LN(x@W1 + b1)) ----------------
__global__ void __launch_bounds__(512) backbone_kernel(
    const float* __restrict__ x, const float* __restrict__ W1,
    const float* __restrict__ b1, const float* __restrict__ ln_g,
    const float* __restrict__ ln_b) {
    __shared__ float xs[E_];
    __shared__ float sred[32];
    int b = blockIdx.x, col = threadIdx.x;
    if (col < E_) xs[col] = x[b * E_ + col];
    __syncthreads();
    float acc = b1[col];
#pragma unroll 4
    for (int e = 0; e < E_; e++) acc = fmaf(xs[e], W1[e * H_ + col], acc);
    float mu = blockReduceSum(acc, sred) * (1.0f / H_);
    float d = acc - mu;
    float var = blockReduceSum(d * d, sred) * (1.0f / H_);
    float nrm = d / sqrtf(var + LN_EPS) * ln_g[col] + ln_b[col];
    float hv = 0.5f * nrm * (1.0f + erff(nrm * 0.70710678118654752f));
    g_h[b * H_ + col] = hv;
    float n2 = blockReduceSum(hv * hv, sred);
    if (col == 0) g_zinv[b] = 1.0f / fmaxf(sqrtf(n2), 1e-12f);
}

// ---------------- A-fragment packing for logits (fp16 single) ----------------
// combo = xtile*8 + wm*2 + mi (16 combos); frag regs: (r,c),(r+8,c),(r,c+8),(r+8,c+8)
__global__ void __launch_bounds__(256) afrag_kernel() {
    int combo = blockIdx.x >> 2;
    int mi = combo & 1, wm = (combo >> 1) & 3, xtile = combo >> 3;
    int ks = ((blockIdx.x & 3) << 3) | (threadIdx.x >> 5);
    int lane = threadIdx.x & 31;
    int r = xtile * 128 + wm * 32 + mi * 16 + (lane >> 2);
    int c = ks * 16 + (lane & 3) * 2;
    const float* Hp = g_h;
    uint4 o;
    o.x = pk2h(Hp[r * H_ + c],           Hp[r * H_ + c + 1]);
    o.y = pk2h(Hp[(r + 8) * H_ + c],     Hp[(r + 8) * H_ + c + 1]);
    o.z = pk2h(Hp[r * H_ + c + 8],       Hp[r * H_ + c + 9]);
    o.w = pk2h(Hp[(r + 8) * H_ + c + 8], Hp[(r + 8) * H_ + c + 9]);
    g_afrag[(size_t)combo * 1024 + ks * 32 + lane] = o;
}

// ---------------- codebook row inverse norms ----------------
__global__ void __launch_bounds__(256) cinv_kernel(const float* __restrict__ C) {
    int warp = blockIdx.x * 8 + (threadIdx.x >> 5);
    int lane = threadIdx.x & 31;
    if (warp >= V_) return;
    const float* row = C + (size_t)warp * H_;
    float ss = 0.f;
#pragma unroll 4
    for (int i = lane; i < H_; i += 32) { float v = row[i]; ss = fmaf(v, v, ss); }
#pragma unroll
    for (int o = 16; o; o >>= 1) ss += __shfl_xor_sync(0xFFFFFFFFu, ss, o);
    if (lane == 0) g_cinv[warp] = 1.0f / fmaxf(sqrtf(ss), 1e-12f);
}

// ---------------- codebook prep: fp16 logits B frags + bf16 CT transpose ----------------
__global__ void __launch_bounds__(256) prep_kernel(const float* __restrict__ C) {
    __shared__ float tile[32][33];   // tile[v-local][h-local]
    int v0 = blockIdx.x * 32, h0 = blockIdx.y * 32;
    int tx = threadIdx.x & 31, ty = threadIdx.x >> 5;
#pragma unroll
    for (int j = 0; j < 4; j++) {
        int v = v0 + ty + j * 8;
        tile[ty + j * 8][tx] = C[(size_t)v * H_ + h0 + tx];
    }
    __syncthreads();
    // CT transpose (bf16, for expected GEMM)
#pragma unroll
    for (int j = 0; j < 4; j++) {
        int h = h0 + ty + j * 8;
        g_CT[(size_t)h * V_ + v0 + tx] = __float2bfloat16(tile[tx][ty + j * 8]);
    }
    // logits B fragment emission (fp16 single): 128 threads = 4 fragblocks x 32 lanes
    if (threadIdx.x < 128) {
        int fb = threadIdx.x >> 5;           // kshalf = fb>>1, nj = fb&1
        int kshalf = fb >> 1, nj = fb & 1;
        int lane = threadIdx.x & 31;
        int nl = nj * 16 + (lane >> 2);
        int kl = kshalf * 16 + (lane & 3) * 2;
        uint4 o;
        o.x = pk2h(tile[nl][kl],         tile[nl][kl + 1]);
        o.y = pk2h(tile[nl][kl + 8],     tile[nl][kl + 9]);
        o.z = pk2h(tile[nl + 8][kl],     tile[nl + 8][kl + 1]);
        o.w = pk2h(tile[nl + 8][kl + 8], tile[nl + 8][kl + 9]);
        int vtile = v0 >> 6, wn = (v0 >> 5) & 1;
        int ks = (h0 >> 4) + kshalf;
        size_t idx = ((((size_t)vtile * 4) + wn * 2 + nj) * 32 + ks) * 32 + lane;
        g_bfrag[idx] = o;
    }
}

// ================= logits GEMM: single-pass fp16, fragment-packed LDG, no smem =================
__global__ void __launch_bounds__(256, 2) logits_mma_kernel(
    const float* __restrict__ lscale, float* __restrict__ out,
    const void* __restrict__ taup, int t) {
    const int tid = threadIdx.x, lane = tid & 31, wid = tid >> 5;
    const int wm = wid >> 1, wn = wid & 1;
    const int xtile = blockIdx.x, vtile = blockIdx.y;
    const int bbase = xtile * 128, vbase = vtile * 64;

    float acc[2][4][4];
#pragma unroll
    for (int i = 0; i < 2; i++)
#pragma unroll
        for (int j = 0; j < 4; j++)
#pragma unroll
            for (int c = 0; c < 4; c++) acc[i][j][c] = 0.f;

    const char* pA = (const char*)g_afrag +
                     ((size_t)(xtile * 8 + wm * 2) * 1024 + lane) * 16;
    const char* pB = (const char*)g_bfrag +
                     (((size_t)vtile * 4 + wn * 2) * 1024 + lane) * 16;

#define LDA(buf, ks) do { \
        buf[0] = *(const uint4*)(pA + (ks) * 512); \
        buf[1] = *(const uint4*)(pA + 16384 + (ks) * 512); \
    } while (0)
#define LDB(buf, ks) do { \
        buf[0] = *(const uint4*)(pB + (ks) * 512); \
        buf[1] = *(const uint4*)(pB + 16384 + (ks) * 512); \
    } while (0)
#define COMPUTE(A_, B_) do { \
        _Pragma("unroll") \
        for (int mi_ = 0; mi_ < 2; mi_++) { \
            const uint32_t* a_ = (const uint32_t*)&A_[mi_]; \
            _Pragma("unroll") \
            for (int nf_ = 0; nf_ < 4; nf_++) { \
                const uint32_t* b_ = ((const uint32_t*)&B_[nf_ >> 1]) + (nf_ & 1) * 2; \
                mma_f16(acc[mi_][nf_], a_, b_); \
            } \
        } \
    } while (0)

    uint4 A0[2], B0[2], A1[2], B1[2];
    LDA(A0, 0); LDB(B0, 0);
#pragma unroll
    for (int ks = 0; ks < 32; ks += 2) {
        if (ks + 1 < 32) { LDA(A1, ks + 1); LDB(B1, ks + 1); }
        COMPUTE(A0, B0);
        if (ks + 2 < 32) { LDA(A0, ks + 2); LDB(B0, ks + 2); }
        if (ks + 1 < 32) COMPUTE(A1, B1);
    }
#undef LDA
#undef LDB
#undef COMPUTE

    // ---- epilogue: logits + gumbel + exp (fp32 + bf16 rows) + per-row partial sums ----
    float scale = expf(__ldg(lscale + t));
    float inv_tau = 1.0f / tau_value(taup);
#pragma unroll
    for (int mi = 0; mi < 2; mi++) {
        int r0 = bbase + wm * 32 + mi * 16 + (lane >> 2);
        int r1 = r0 + 8;
        float z0 = g_zinv[r0], z1 = g_zinv[r1];
        float* row0 = out + (((size_t)r0 * T_ + t) << 15);
        float* row1 = out + (((size_t)r1 * T_ + t) << 15);
        float* e0 = g_expv + (size_t)r0 * V_;
        float* e1 = g_expv + (size_t)r1 * V_;
        __nv_bfloat16* be0 = g_e_bf16 + (size_t)r0 * V_;
        __nv_bfloat16* be1 = g_e_bf16 + (size_t)r1 * V_;
        float s0 = 0.f, s1 = 0.f;
#pragma unroll
        for (int nf = 0; nf < 4; nf++) {
            int v0 = vbase + wn * 32 + nf * 8 + (lane & 3) * 2;
            float cv0 = g_cinv[v0] * scale, cv1 = g_cinv[v0 + 1] * scale;
            float l00 = acc[mi][nf][0] * z0 * cv0, l01 = acc[mi][nf][1] * z0 * cv1;
            float l10 = acc[mi][nf][2] * z1 * cv0, l11 = acc[mi][nf][3] * z1 * cv1;
            *(float2*)(row0 + v0) = make_float2(l00, l01);
            *(float2*)(row1 + v0) = make_float2(l10, l11);
            float e00 = __expf((l00 + gumbel_val(t, r0, v0))     * inv_tau);
            float e01 = __expf((l01 + gumbel_val(t, r0, v0 + 1)) * inv_tau);
            float e10 = __expf((l10 + gumbel_val(t, r1, v0))     * inv_tau);
            float e11 = __expf((l11 + gumbel_val(t, r1, v0 + 1)) * inv_tau);
            *(float2*)(e0 + v0) = make_float2(e00, e01);
            *(float2*)(e1 + v0) = make_float2(e10, e11);
            *(__nv_bfloat162*)(be0 + v0) = __floats2bfloat162_rn(e00, e01);
            *(__nv_bfloat162*)(be1 + v0) = __floats2bfloat162_rn(e10, e11);
            s0 += e00 + e01;
            s1 += e10 + e11;
        }
        s0 += __shfl_xor_sync(0xFFFFFFFFu, s0, 1);
        s0 += __shfl_xor_sync(0xFFFFFFFFu, s0, 2);
        s1 += __shfl_xor_sync(0xFFFFFFFFu, s1, 1);
        s1 += __shfl_xor_sync(0xFFFFFFFFu, s1, 2);
        if ((lane & 3) == 0) {
            g_psum[((size_t)r0 * 512 + vtile) * 2 + wn] = s0;
            g_psum[((size_t)r1 * 512 + vtile) * 2 + wn] = s1;
        }
    }
}

// ---------------- row sums (deterministic, tiny) ----------------
__global__ void __launch_bounds__(256) rowsum_kernel() {
    int b = blockIdx.x * 8 + (threadIdx.x >> 5);
    int lane = threadIdx.x & 31;
    const float* p = g_psum + (size_t)b * 1024;
    float s = 0.f;
#pragma unroll
    for (int i = 0; i < 32; i++) s += p[lane + i * 32];
#pragma unroll
    for (int o = 16; o; o >>= 1) s += __shfl_xor_sync(0xFFFFFFFFu, s, o);
    if (lane == 0) g_rsum[b] = 1.0f / s;
}

// ---------------- normalize: p = e * rsum (fp32 probs output only, wide grid) ----------------
__global__ void __launch_bounds__(256) normalize_kernel(float* __restrict__ outw, int t) {
    int i = (blockIdx.x * 256 + threadIdx.x) * 4;
    int b = i >> 15, v = i & (V_ - 1);
    float4 e = *(const float4*)(g_expv + (size_t)b * V_ + v);
    float rs = g_rsum[b];
    *(float4*)(outw + (size_t)B_ * T_ * V_ + (((size_t)b * T_ + t) << 15) + v) =
        make_float4(e.x * rs, e.y * rs, e.z * rs, e.w * rs);
}

// ================= expected GEMM (mma.sync bf16, split-K=32, consumes raw e) =================
#define EX_STAGE 24576
#define EX_SMEM (2 * EX_STAGE)
__global__ void __launch_bounds__(256, 2) expected_mma_kernel() {
    extern __shared__ char smem[];
    const uint32_t sb = smem_u32(smem);
    const int tid = threadIdx.x, lane = tid & 31, wid = tid >> 5;
    const int wm = wid >> 1, wn = wid & 1;
    const int hbase = blockIdx.x * 64, bbase = blockIdx.y * 128;
    const int z = blockIdx.z;
    const int kz = z * (V_ / ZSPLIT);   // 1024

    float acc[2][4][4];
#pragma unroll
    for (int i = 0; i < 2; i++)
#pragma unroll
        for (int j = 0; j < 4; j++)
#pragma unroll
            for (int c = 0; c < 4; c++) acc[i][j][c] = 0.f;

    const int lr = tid >> 3;
    const int lc = tid & 7;

#define LOAD_STAGE(s, k0) do { \
        uint32_t st_ = sb + (s) * EX_STAGE; \
        _Pragma("unroll") \
        for (int i_ = 0; i_ < 4; i_++) { \
            int r_ = lr + i_ * 32; \
            uint32_t sw_ = ((uint32_t)(r_ * 128 + lc * 16)) ^ (((uint32_t)r_ & 7u) << 4); \
            cp16(st_ + sw_, g_e_bf16 + (size_t)(bbase + r_) * V_ + (k0) + lc * 8); \
        } \
        _Pragma("unroll") \
        for (int i_ = 0; i_ < 2; i_++) { \
            int r_ = lr + i_ * 32; \
            uint32_t sw_ = ((uint32_t)(r_ * 128 + lc * 16)) ^ (((uint32_t)r_ & 7u) << 4); \
            cp16(st_ + 16384 + sw_, g_CT + (size_t)(hbase + r_) * V_ + (k0) + lc * 8); \
        } \
        CP_COMMIT(); \
    } while (0)

    LOAD_STAGE(0, kz);
    LOAD_STAGE(1, kz + 64);

    const int arow = wm * 32 + (lane & 7) + ((lane >> 3) & 1) * 8;
    const int acol = (lane >> 4);
    const int brow = wn * 32 + (lane & 7) + (lane >> 4) * 8;
    const int bcol = ((lane >> 3) & 1);

    for (int kt = 0; kt < 16; kt++) {
        CP_WAIT1();
        __syncthreads();
        uint32_t st = sb + (kt & 1) * EX_STAGE;
#pragma unroll
        for (int ks = 0; ks < 4; ks++) {
            uint32_t a[2][4], b[2][4];
#pragma unroll
            for (int mi = 0; mi < 2; mi++) {
                int r = arow + mi * 16;
                uint32_t off = ((uint32_t)(r * 128 + (acol + ks * 2) * 16)) ^ (((uint32_t)r & 7u) << 4);
                ldsm4(a[mi], st + off);
            }
#pragma unroll
            for (int nj = 0; nj < 2; nj++) {
                int r = brow + nj * 16;
                uint32_t off = ((uint32_t)(r * 128 + (bcol + ks * 2) * 16)) ^ (((uint32_t)r & 7u) << 4);
                ldsm4(b[nj], st + 16384 + off);
            }
#pragma unroll
            for (int mi = 0; mi < 2; mi++)
#pragma unroll
                for (int nf = 0; nf < 4; nf++)
                    mma_bf16(acc[mi][nf], a[mi], &b[nf >> 1][(nf & 1) * 2]);
        }
        __syncthreads();
        if (kt < 14) LOAD_STAGE(kt & 1, kz + (kt + 2) * 64);
        else CP_COMMIT();
    }
#undef LOAD_STAGE

#pragma unroll
    for (int mi = 0; mi < 2; mi++) {
        int r0 = bbase + wm * 32 + mi * 16 + (lane >> 2);
        float* p0 = g_partial + ((size_t)z * B_ + r0) * H_ + hbase;
        float* p1 = g_partial + ((size_t)z * B_ + r0 + 8) * H_ + hbase;
#pragma unroll
        for (int nf = 0; nf < 4; nf++) {
            int h0 = wn * 32 + nf * 8 + (lane & 3) * 2;
            *(float2*)(p0 + h0) = make_float2(acc[mi][nf][0], acc[mi][nf][1]);
            *(float2*)(p1 + h0) = make_float2(acc[mi][nf][2], acc[mi][nf][3]);
        }
    }
}

// ---------------- residual update + RMSNorm (folds exp(gamma)*rsum into raw-e sums) ----------------
__global__ void __launch_bounds__(512) update_kernel(
    const float* __restrict__ gamma, const float* __restrict__ rms_w, int t) {
    __shared__ float sred[32];
    int b = blockIdx.x, h = threadIdx.x;
    float e = 0.f;
#pragma unroll
    for (int s = 0; s < ZSPLIT; s++) e += g_partial[((size_t)s * B_ + b) * H_ + h];
    float eg = expf(gamma[t]) * g_rsum[b];
    float hn = g_h[b * H_ + h] - eg * e;
    float ss = blockReduceSum(hn * hn, sred);
    float denom = sqrtf(ss * (1.0f / H_) + RMS_EPS);
    float hv = hn / denom * rms_w[h];
    g_h[b * H_ + h] = hv;
    float n2 = blockReduceSum(hv * hv, sred);
    if (h == 0) g_zinv[b] = 1.0f / fmaxf(sqrtf(n2), 1e-12f);
}

// ---------------- launch ----------------
extern "C" void kernel_launch(void* const* d_in, const int* in_sizes, int n_in,
                              void* d_out, int out_size) {
    const float* x           = (const float*)d_in[0];
    const float* W1          = (const float*)d_in[1];
    const float* b1          = (const float*)d_in[2];
    const float* ln_g        = (const float*)d_in[3];
    const float* ln_b        = (const float*)d_in[4];
    const float* codebook    = (const float*)d_in[5];
    const float* logit_scale = (const float*)d_in[6];
    const float* gamma       = (const float*)d_in[7];
    const float* rms_w       = (const float*)d_in[8];
    const void*  tau         = d_in[9];
    float* out = (float*)d_out;

    cudaFuncSetAttribute(expected_mma_kernel, cudaFuncAttributeMaxDynamicSharedMemorySize, EX_SMEM);

    const long long logitsElems = (long long)B_ * T_ * V_;
    int writeProbs = ((long long)out_size >= 2 * logitsElems) ? 1 : 0;

    backbone_kernel<<<B_, 512>>>(x, W1, b1, ln_g, ln_b);
    cinv_kernel<<<V_ / 8, 256>>>(codebook);
    prep_kernel<<<dim3(V_ / 32, H_ / 32), 256>>>(codebook);
    afrag_kernel<<<64, 256>>>();

    for (int t = 0; t < T_; t++) {
        logits_mma_kernel<<<dim3(B_ / 128, V_ / 64), 256>>>(logit_scale, out, tau, t);
        rowsum_kernel<<<B_ / 8, 256>>>();
        if (writeProbs) normalize_kernel<<<(B_ * V_ / 4) / 256, 256>>>(out, t);
        if (t < T_ - 1) {
            expected_mma_kernel<<<dim3(H_ / 64, B_ / 128, ZSPLIT), 256, EX_SMEM>>>();
            update_kernel<<<B_, 512>>>(gamma, rms_w, t);
            afrag_kernel<<<64, 256>>>();
        }
    }
}

// round 16
// speedup vs baseline: 1.3552x; 1.0329x over previous
#include <cuda_runtime.h>
#include <cuda_bf16.h>
#include <cuda_fp16.h>
#include <cstdint>
#include <math.h>

// Problem constants
#define B_  256
#define E_  256
#define H_  512
#define V_  32768
#define T_  8
#define LN_EPS 1e-5f
#define RMS_EPS 1.1920928955078125e-7f   // finfo(f32).eps
#define TINY_F 1.17549435e-38f

#define ZSPLIT 32                         // split-K factor for expected GEMM

// ---------------- device scratch (static, allocation-free) ----------------
__device__ __align__(16) float g_h[B_ * H_];                 // residual h (fp32 exact)
__device__ float g_zinv[B_];
__device__ float g_cinv[V_];
__device__ __align__(16) uint4 g_afrag[16 * 1024];           // logits A frags (fp16)
__device__ __align__(16) uint4 g_bfrag[(size_t)512 * 4 * 32 * 32];  // logits B frags fp16 (32MB)
__device__ __align__(16) __nv_bfloat16 g_CT[(size_t)H_ * V_];     // codebook^T bf16 [H][V]
__device__ __align__(16) __nv_bfloat16 g_e_bf16[(size_t)B_ * V_]; // bf16(raw e) for expected GEMM
__device__ __align__(16) float g_partial[ZSPLIT * B_ * H_];       // split-K partials (raw-e sums)
__device__ __align__(16) float g_expv[(size_t)B_ * V_];           // exp((l+g)/tau) fp32
__device__ __align__(16) float g_psum[B_ * 512 * 2];              // per (b, vtile, wn) sums
__device__ float g_rsum[B_];                                       // 1/rowsum

// ================= PTX helpers (base ISA only) =================
__device__ __forceinline__ uint32_t smem_u32(const void* p) {
    uint32_t a;
    asm("{ .reg .u64 t; cvta.to.shared.u64 t, %1; cvt.u32.u64 %0, t; }" : "=r"(a) : "l"(p));
    return a;
}
__device__ __forceinline__ void cp16(uint32_t dst, const void* src) {
    asm volatile("cp.async.cg.shared.global [%0], [%1], 16;" :: "r"(dst), "l"(src) : "memory");
}
#define CP_COMMIT() asm volatile("cp.async.commit_group;" ::: "memory")
#define CP_WAIT1()  asm volatile("cp.async.wait_group 1;" ::: "memory")

__device__ __forceinline__ void ldsm4(uint32_t* r, uint32_t addr) {
    asm volatile("ldmatrix.sync.aligned.m8n8.x4.shared.b16 {%0,%1,%2,%3}, [%4];"
                 : "=r"(r[0]), "=r"(r[1]), "=r"(r[2]), "=r"(r[3]) : "r"(addr));
}
__device__ __forceinline__ void mma_bf16(float* d, const uint32_t* a, const uint32_t* b) {
    asm volatile(
        "mma.sync.aligned.m16n8k16.row.col.f32.bf16.bf16.f32 "
        "{%0,%1,%2,%3}, {%4,%5,%6,%7}, {%8,%9}, {%0,%1,%2,%3};"
        : "+f"(d[0]), "+f"(d[1]), "+f"(d[2]), "+f"(d[3])
        : "r"(a[0]), "r"(a[1]), "r"(a[2]), "r"(a[3]), "r"(b[0]), "r"(b[1]));
}
__device__ __forceinline__ void mma_f16(float* d, const uint32_t* a, const uint32_t* b) {
    asm volatile(
        "mma.sync.aligned.m16n8k16.row.col.f32.f16.f16.f32 "
        "{%0,%1,%2,%3}, {%4,%5,%6,%7}, {%8,%9}, {%0,%1,%2,%3};"
        : "+f"(d[0]), "+f"(d[1]), "+f"(d[2]), "+f"(d[3])
        : "r"(a[0]), "r"(a[1]), "r"(a[2]), "r"(a[3]), "r"(b[0]), "r"(b[1]));
}
__device__ __forceinline__ uint32_t pk2h(float a, float b) {
    __half2 t;
    t.x = __float2half(a); t.y = __float2half(b);
    return *(uint32_t*)&t;
}

// store h value pair into logits A-fragment layout (called by even-h threads)
__device__ __forceinline__ void store_afrag(int b, int h, float v0, float v1) {
    int combo = ((b >> 7) << 3) | (((b >> 5) & 3) << 1) | ((b >> 4) & 1);
    int ks = h >> 4;
    int lane = ((b & 7) << 2) | ((h >> 1) & 3);
    int comp = (((h & 15) >> 3) << 1) | ((b & 15) >> 3);   // 0:x 1:y 2:z 3:w
    uint32_t* p = (uint32_t*)(g_afrag + (size_t)combo * 1024 + ks * 32 + lane) + comp;
    *p = pk2h(v0, v1);
}

// ---------------- reductions ----------------
__device__ __forceinline__ float blockReduceSum(float v, float* sh) {
    __syncthreads();
    int lane = threadIdx.x & 31, wid = threadIdx.x >> 5;
#pragma unroll
    for (int o = 16; o; o >>= 1) v += __shfl_xor_sync(0xFFFFFFFFu, v, o);
    if (lane == 0) sh[wid] = v;
    __syncthreads();
    int nw = blockDim.x >> 5;
    if (wid == 0) {
        float s = (lane < nw) ? sh[lane] : 0.f;
#pragma unroll
        for (int o = 16; o; o >>= 1) s += __shfl_xor_sync(0xFFFFFFFFu, s, o);
        if (lane == 0) sh[0] = s;
    }
    __syncthreads();
    float r = sh[0];
    __syncthreads();
    return r;
}

// ---------------- Threefry-2x32 (JAX partitionable, key=(0,42)) ----------------
__device__ __forceinline__ unsigned rotl32(unsigned x, int r) { return __funnelshift_l(x, x, r); }
__device__ __forceinline__ uint2 tf2x32(unsigned x0, unsigned x1) {
    const unsigned k0 = 0u, k1 = 42u;
    const unsigned k2 = k0 ^ k1 ^ 0x1BD11BDAu;
    x0 += k0; x1 += k1;
#define TFR(r) { x0 += x1; x1 = rotl32(x1, r); x1 ^= x0; }
    TFR(13) TFR(15) TFR(26) TFR(6)
    x0 += k1; x1 += k2 + 1u;
    TFR(17) TFR(29) TFR(16) TFR(24)
    x0 += k2; x1 += k0 + 2u;
    TFR(13) TFR(15) TFR(26) TFR(6)
    x0 += k0; x1 += k1 + 3u;
    TFR(17) TFR(29) TFR(16) TFR(24)
    x0 += k1; x1 += k2 + 4u;
    TFR(13) TFR(15) TFR(26) TFR(6)
    x0 += k2; x1 += k0 + 5u;
#undef TFR
    return make_uint2(x0, x1);
}
// gumbel = -log(-log(u)); exact-argument log1p poly near u->1, __logf elsewhere.
__device__ __forceinline__ float gumbel_val(unsigned t, unsigned b, unsigned v) {
    unsigned f = (((t << 8) | b) << 15) | v;
    uint2 r = tf2x32(0u, f);
    unsigned bits = r.x ^ r.y;
    unsigned m = bits >> 9;
    float x = __uint_as_float(0x3F800000u | m);
    float u = x - 1.0f;                 // uniform in [0,1), exact
    float d = x - 2.0f;                 // u - 1, exact
    float p = fmaf(-0.25f, d, 0.33333333f);
    p = fmaf(p, d, -0.5f);
    p = fmaf(p, d, 1.0f);
    p = -p * d;
    float l = -__logf(u);
    float y = (d > -0.0625f) ? p : l;
    y = (m == 0u) ? 87.3365448f : y;
    return -__logf(y);
}
__device__ __forceinline__ float tau_value(const void* p) {
    int i = *(const int*)p;
    float f = __int_as_float(i);
    if (f > 1e-3f && f < 1e6f) return f;
    return (float)i;
}

// ---------------- backbone: h = GELU(LN(x@W1 + b1)) + A-frag store ----------------
__global__ void __launch_bounds__(512) backbone_kernel(
    const float* __restrict__ x, const float* __restrict__ W1,
    const float* __restrict__ b1, const float* __restrict__ ln_g,
    const float* __restrict__ ln_b) {
    __shared__ float xs[E_];
    __shared__ float sred[32];
    int b = blockIdx.x, col = threadIdx.x;
    if (col < E_) xs[col] = x[b * E_ + col];
    __syncthreads();
    float acc = b1[col];
#pragma unroll 4
    for (int e = 0; e < E_; e++) acc = fmaf(xs[e], W1[e * H_ + col], acc);
    float mu = blockReduceSum(acc, sred) * (1.0f / H_);
    float d = acc - mu;
    float var = blockReduceSum(d * d, sred) * (1.0f / H_);
    float nrm = d / sqrtf(var + LN_EPS) * ln_g[col] + ln_b[col];
    float hv = 0.5f * nrm * (1.0f + erff(nrm * 0.70710678118654752f));
    g_h[b * H_ + col] = hv;
    float hnext = __shfl_down_sync(0xFFFFFFFFu, hv, 1);
    if (!(col & 1)) store_afrag(b, col, hv, hnext);
    float n2 = blockReduceSum(hv * hv, sred);
    if (col == 0) g_zinv[b] = 1.0f / fmaxf(sqrtf(n2), 1e-12f);
}

// ---------------- codebook row inverse norms ----------------
__global__ void __launch_bounds__(256) cinv_kernel(const float* __restrict__ C) {
    int warp = blockIdx.x * 8 + (threadIdx.x >> 5);
    int lane = threadIdx.x & 31;
    if (warp >= V_) return;
    const float* row = C + (size_t)warp * H_;
    float ss = 0.f;
#pragma unroll 4
    for (int i = lane; i < H_; i += 32) { float v = row[i]; ss = fmaf(v, v, ss); }
#pragma unroll
    for (int o = 16; o; o >>= 1) ss += __shfl_xor_sync(0xFFFFFFFFu, ss, o);
    if (lane == 0) g_cinv[warp] = 1.0f / fmaxf(sqrtf(ss), 1e-12f);
}

// ---------------- codebook prep: fp16 logits B frags + bf16 CT transpose ----------------
__global__ void __launch_bounds__(256) prep_kernel(const float* __restrict__ C) {
    __shared__ float tile[32][33];   // tile[v-local][h-local]
    int v0 = blockIdx.x * 32, h0 = blockIdx.y * 32;
    int tx = threadIdx.x & 31, ty = threadIdx.x >> 5;
#pragma unroll
    for (int j = 0; j < 4; j++) {
        int v = v0 + ty + j * 8;
        tile[ty + j * 8][tx] = C[(size_t)v * H_ + h0 + tx];
    }
    __syncthreads();
    // CT transpose (bf16, for expected GEMM)
#pragma unroll
    for (int j = 0; j < 4; j++) {
        int h = h0 + ty + j * 8;
        g_CT[(size_t)h * V_ + v0 + tx] = __float2bfloat16(tile[tx][ty + j * 8]);
    }
    // logits B fragment emission (fp16 single): 128 threads = 4 fragblocks x 32 lanes
    if (threadIdx.x < 128) {
        int fb = threadIdx.x >> 5;           // kshalf = fb>>1, nj = fb&1
        int kshalf = fb >> 1, nj = fb & 1;
        int lane = threadIdx.x & 31;
        int nl = nj * 16 + (lane >> 2);
        int kl = kshalf * 16 + (lane & 3) * 2;
        uint4 o;
        o.x = pk2h(tile[nl][kl],         tile[nl][kl + 1]);
        o.y = pk2h(tile[nl][kl + 8],     tile[nl][kl + 9]);
        o.z = pk2h(tile[nl + 8][kl],     tile[nl + 8][kl + 1]);
        o.w = pk2h(tile[nl + 8][kl + 8], tile[nl + 8][kl + 9]);
        int vtile = v0 >> 6, wn = (v0 >> 5) & 1;
        int ks = (h0 >> 4) + kshalf;
        size_t idx = ((((size_t)vtile * 4) + wn * 2 + nj) * 32 + ks) * 32 + lane;
        g_bfrag[idx] = o;
    }
}

// ================= logits GEMM: single-pass fp16, fragment-packed LDG, no smem =================
__global__ void __launch_bounds__(256, 2) logits_mma_kernel(
    const float* __restrict__ lscale, float* __restrict__ out,
    const void* __restrict__ taup, int t) {
    const int tid = threadIdx.x, lane = tid & 31, wid = tid >> 5;
    const int wm = wid >> 1, wn = wid & 1;
    const int xtile = blockIdx.x, vtile = blockIdx.y;
    const int bbase = xtile * 128, vbase = vtile * 64;

    float acc[2][4][4];
#pragma unroll
    for (int i = 0; i < 2; i++)
#pragma unroll
        for (int j = 0; j < 4; j++)
#pragma unroll
            for (int c = 0; c < 4; c++) acc[i][j][c] = 0.f;

    const char* pA = (const char*)g_afrag +
                     ((size_t)(xtile * 8 + wm * 2) * 1024 + lane) * 16;
    const char* pB = (const char*)g_bfrag +
                     (((size_t)vtile * 4 + wn * 2) * 1024 + lane) * 16;

#define LDA(buf, ks) do { \
        buf[0] = *(const uint4*)(pA + (ks) * 512); \
        buf[1] = *(const uint4*)(pA + 16384 + (ks) * 512); \
    } while (0)
#define LDB(buf, ks) do { \
        buf[0] = *(const uint4*)(pB + (ks) * 512); \
        buf[1] = *(const uint4*)(pB + 16384 + (ks) * 512); \
    } while (0)
#define COMPUTE(A_, B_) do { \
        _Pragma("unroll") \
        for (int mi_ = 0; mi_ < 2; mi_++) { \
            const uint32_t* a_ = (const uint32_t*)&A_[mi_]; \
            _Pragma("unroll") \
            for (int nf_ = 0; nf_ < 4; nf_++) { \
                const uint32_t* b_ = ((const uint32_t*)&B_[nf_ >> 1]) + (nf_ & 1) * 2; \
                mma_f16(acc[mi_][nf_], a_, b_); \
            } \
        } \
    } while (0)

    uint4 A0[2], B0[2], A1[2], B1[2];
    LDA(A0, 0); LDB(B0, 0);
#pragma unroll
    for (int ks = 0; ks < 32; ks += 2) {
        if (ks + 1 < 32) { LDA(A1, ks + 1); LDB(B1, ks + 1); }
        COMPUTE(A0, B0);
        if (ks + 2 < 32) { LDA(A0, ks + 2); LDB(B0, ks + 2); }
        if (ks + 1 < 32) COMPUTE(A1, B1);
    }
#undef LDA
#undef LDB
#undef COMPUTE

    // ---- epilogue: logits + gumbel + exp (fp32 + bf16 rows) + per-row partial sums ----
    float scale = expf(__ldg(lscale + t));
    float inv_tau = 1.0f / tau_value(taup);
#pragma unroll
    for (int mi = 0; mi < 2; mi++) {
        int r0 = bbase + wm * 32 + mi * 16 + (lane >> 2);
        int r1 = r0 + 8;
        float z0 = g_zinv[r0], z1 = g_zinv[r1];
        float* row0 = out + (((size_t)r0 * T_ + t) << 15);
        float* row1 = out + (((size_t)r1 * T_ + t) << 15);
        float* e0 = g_expv + (size_t)r0 * V_;
        float* e1 = g_expv + (size_t)r1 * V_;
        __nv_bfloat16* be0 = g_e_bf16 + (size_t)r0 * V_;
        __nv_bfloat16* be1 = g_e_bf16 + (size_t)r1 * V_;
        float s0 = 0.f, s1 = 0.f;
#pragma unroll
        for (int nf = 0; nf < 4; nf++) {
            int v0 = vbase + wn * 32 + nf * 8 + (lane & 3) * 2;
            float cv0 = g_cinv[v0] * scale, cv1 = g_cinv[v0 + 1] * scale;
            float l00 = acc[mi][nf][0] * z0 * cv0, l01 = acc[mi][nf][1] * z0 * cv1;
            float l10 = acc[mi][nf][2] * z1 * cv0, l11 = acc[mi][nf][3] * z1 * cv1;
            *(float2*)(row0 + v0) = make_float2(l00, l01);
            *(float2*)(row1 + v0) = make_float2(l10, l11);
            float e00 = __expf((l00 + gumbel_val(t, r0, v0))     * inv_tau);
            float e01 = __expf((l01 + gumbel_val(t, r0, v0 + 1)) * inv_tau);
            float e10 = __expf((l10 + gumbel_val(t, r1, v0))     * inv_tau);
            float e11 = __expf((l11 + gumbel_val(t, r1, v0 + 1)) * inv_tau);
            *(float2*)(e0 + v0) = make_float2(e00, e01);
            *(float2*)(e1 + v0) = make_float2(e10, e11);
            *(__nv_bfloat162*)(be0 + v0) = __floats2bfloat162_rn(e00, e01);
            *(__nv_bfloat162*)(be1 + v0) = __floats2bfloat162_rn(e10, e11);
            s0 += e00 + e01;
            s1 += e10 + e11;
        }
        s0 += __shfl_xor_sync(0xFFFFFFFFu, s0, 1);
        s0 += __shfl_xor_sync(0xFFFFFFFFu, s0, 2);
        s1 += __shfl_xor_sync(0xFFFFFFFFu, s1, 1);
        s1 += __shfl_xor_sync(0xFFFFFFFFu, s1, 2);
        if ((lane & 3) == 0) {
            g_psum[((size_t)r0 * 512 + vtile) * 2 + wn] = s0;
            g_psum[((size_t)r1 * 512 + vtile) * 2 + wn] = s1;
        }
    }
}

// ---------------- row sums (deterministic, tiny) ----------------
__global__ void __launch_bounds__(256) rowsum_kernel() {
    int b = blockIdx.x * 8 + (threadIdx.x >> 5);
    int lane = threadIdx.x & 31;
    const float* p = g_psum + (size_t)b * 1024;
    float s = 0.f;
#pragma unroll
    for (int i = 0; i < 32; i++) s += p[lane + i * 32];
#pragma unroll
    for (int o = 16; o; o >>= 1) s += __shfl_xor_sync(0xFFFFFFFFu, s, o);
    if (lane == 0) g_rsum[b] = 1.0f / s;
}

// ---------------- normalize: p = e * rsum (fp32 probs output only, wide grid) ----------------
__global__ void __launch_bounds__(256) normalize_kernel(float* __restrict__ outw, int t) {
    int i = (blockIdx.x * 256 + threadIdx.x) * 4;
    int b = i >> 15, v = i & (V_ - 1);
    float4 e = *(const float4*)(g_expv + (size_t)b * V_ + v);
    float rs = g_rsum[b];
    *(float4*)(outw + (size_t)B_ * T_ * V_ + (((size_t)b * T_ + t) << 15) + v) =
        make_float4(e.x * rs, e.y * rs, e.z * rs, e.w * rs);
}

// ================= expected GEMM (mma.sync bf16, split-K=32, consumes raw e) =================
#define EX_STAGE 24576
#define EX_SMEM (2 * EX_STAGE)
__global__ void __launch_bounds__(256, 2) expected_mma_kernel() {
    extern __shared__ char smem[];
    const uint32_t sb = smem_u32(smem);
    const int tid = threadIdx.x, lane = tid & 31, wid = tid >> 5;
    const int wm = wid >> 1, wn = wid & 1;
    const int hbase = blockIdx.x * 64, bbase = blockIdx.y * 128;
    const int z = blockIdx.z;
    const int kz = z * (V_ / ZSPLIT);   // 1024

    float acc[2][4][4];
#pragma unroll
    for (int i = 0; i < 2; i++)
#pragma unroll
        for (int j = 0; j < 4; j++)
#pragma unroll
            for (int c = 0; c < 4; c++) acc[i][j][c] = 0.f;

    const int lr = tid >> 3;
    const int lc = tid & 7;

#define LOAD_STAGE(s, k0) do { \
        uint32_t st_ = sb + (s) * EX_STAGE; \
        _Pragma("unroll") \
        for (int i_ = 0; i_ < 4; i_++) { \
            int r_ = lr + i_ * 32; \
            uint32_t sw_ = ((uint32_t)(r_ * 128 + lc * 16)) ^ (((uint32_t)r_ & 7u) << 4); \
            cp16(st_ + sw_, g_e_bf16 + (size_t)(bbase + r_) * V_ + (k0) + lc * 8); \
        } \
        _Pragma("unroll") \
        for (int i_ = 0; i_ < 2; i_++) { \
            int r_ = lr + i_ * 32; \
            uint32_t sw_ = ((uint32_t)(r_ * 128 + lc * 16)) ^ (((uint32_t)r_ & 7u) << 4); \
            cp16(st_ + 16384 + sw_, g_CT + (size_t)(hbase + r_) * V_ + (k0) + lc * 8); \
        } \
        CP_COMMIT(); \
    } while (0)

    LOAD_STAGE(0, kz);
    LOAD_STAGE(1, kz + 64);

    const int arow = wm * 32 + (lane & 7) + ((lane >> 3) & 1) * 8;
    const int acol = (lane >> 4);
    const int brow = wn * 32 + (lane & 7) + (lane >> 4) * 8;
    const int bcol = ((lane >> 3) & 1);

    for (int kt = 0; kt < 16; kt++) {
        CP_WAIT1();
        __syncthreads();
        uint32_t st = sb + (kt & 1) * EX_STAGE;
#pragma unroll
        for (int ks = 0; ks < 4; ks++) {
            uint32_t a[2][4], b[2][4];
#pragma unroll
            for (int mi = 0; mi < 2; mi++) {
                int r = arow + mi * 16;
                uint32_t off = ((uint32_t)(r * 128 + (acol + ks * 2) * 16)) ^ (((uint32_t)r & 7u) << 4);
                ldsm4(a[mi], st + off);
            }
#pragma unroll
            for (int nj = 0; nj < 2; nj++) {
                int r = brow + nj * 16;
                uint32_t off = ((uint32_t)(r * 128 + (bcol + ks * 2) * 16)) ^ (((uint32_t)r & 7u) << 4);
                ldsm4(b[nj], st + 16384 + off);
            }
#pragma unroll
            for (int mi = 0; mi < 2; mi++)
#pragma unroll
                for (int nf = 0; nf < 4; nf++)
                    mma_bf16(acc[mi][nf], a[mi], &b[nf >> 1][(nf & 1) * 2]);
        }
        __syncthreads();
        if (kt < 14) LOAD_STAGE(kt & 1, kz + (kt + 2) * 64);
        else CP_COMMIT();
    }
#undef LOAD_STAGE

#pragma unroll
    for (int mi = 0; mi < 2; mi++) {
        int r0 = bbase + wm * 32 + mi * 16 + (lane >> 2);
        float* p0 = g_partial + ((size_t)z * B_ + r0) * H_ + hbase;
        float* p1 = g_partial + ((size_t)z * B_ + r0 + 8) * H_ + hbase;
#pragma unroll
        for (int nf = 0; nf < 4; nf++) {
            int h0 = wn * 32 + nf * 8 + (lane & 3) * 2;
            *(float2*)(p0 + h0) = make_float2(acc[mi][nf][0], acc[mi][nf][1]);
            *(float2*)(p1 + h0) = make_float2(acc[mi][nf][2], acc[mi][nf][3]);
        }
    }
}

// ---------------- residual update + RMSNorm + A-frag store ----------------
__global__ void __launch_bounds__(512) update_kernel(
    const float* __restrict__ gamma, const float* __restrict__ rms_w, int t) {
    __shared__ float sred[32];
    int b = blockIdx.x, h = threadIdx.x;
    float e = 0.f;
#pragma unroll
    for (int s = 0; s < ZSPLIT; s++) e += g_partial[((size_t)s * B_ + b) * H_ + h];
    float eg = expf(gamma[t]) * g_rsum[b];
    float hn = g_h[b * H_ + h] - eg * e;
    float ss = blockReduceSum(hn * hn, sred);
    float denom = sqrtf(ss * (1.0f / H_) + RMS_EPS);
    float hv = hn / denom * rms_w[h];
    g_h[b * H_ + h] = hv;
    float hnext = __shfl_down_sync(0xFFFFFFFFu, hv, 1);
    if (!(h & 1)) store_afrag(b, h, hv, hnext);
    float n2 = blockReduceSum(hv * hv, sred);
    if (h == 0) g_zinv[b] = 1.0f / fmaxf(sqrtf(n2), 1e-12f);
}

// ---------------- launch ----------------
extern "C" void kernel_launch(void* const* d_in, const int* in_sizes, int n_in,
                              void* d_out, int out_size) {
    const float* x           = (const float*)d_in[0];
    const float* W1          = (const float*)d_in[1];
    const float* b1          = (const float*)d_in[2];
    const float* ln_g        = (const float*)d_in[3];
    const float* ln_b        = (const float*)d_in[4];
    const float* codebook    = (const float*)d_in[5];
    const float* logit_scale = (const float*)d_in[6];
    const float* gamma       = (const float*)d_in[7];
    const float* rms_w       = (const float*)d_in[8];
    const void*  tau         = d_in[9];
    float* out = (float*)d_out;

    cudaFuncSetAttribute(expected_mma_kernel, cudaFuncAttributeMaxDynamicSharedMemorySize, EX_SMEM);

    const long long logitsElems = (long long)B_ * T_ * V_;
    int writeProbs = ((long long)out_size >= 2 * logitsElems) ? 1 : 0;

    backbone_kernel<<<B_, 512>>>(x, W1, b1, ln_g, ln_b);
    cinv_kernel<<<V_ / 8, 256>>>(codebook);
    prep_kernel<<<dim3(V_ / 32, H_ / 32), 256>>>(codebook);

    for (int t = 0; t < T_; t++) {
        logits_mma_kernel<<<dim3(B_ / 128, V_ / 64), 256>>>(logit_scale, out, tau, t);
        rowsum_kernel<<<B_ / 8, 256>>>();
        if (writeProbs) normalize_kernel<<<(B_ * V_ / 4) / 256, 256>>>(out, t);
        if (t < T_ - 1) {
            expected_mma_kernel<<<dim3(H_ / 64, B_ / 128, ZSPLIT), 256, EX_SMEM>>>();
            update_kernel<<<B_, 512>>>(gamma, rms_w, t);
        }
    }
}